// round 15
// baseline (speedup 1.0000x reference)
#include <cuda_runtime.h>
#include <cuda_bf16.h>
#include <cstdint>
#include <cstddef>

#define BATCH 8
#define CHN   512
#define SEQ   4096

// ---------------------------------------------------------------------------
// Device scratch (allocation-free rule: __device__ globals)
// ---------------------------------------------------------------------------
static __device__ __align__(256) __nv_bfloat16 g_x_hi [BATCH * CHN * SEQ];  // [b][c][l]
static __device__ __align__(256) __nv_bfloat16 g_xT_hi[BATCH * SEQ * CHN];  // [b][l][c]
static __device__ __align__(256) __nv_bfloat16 g_xT_lo[BATCH * SEQ * CHN];
static __device__ __align__(256) float         g_logits[BATCH * CHN * CHN]; // [b][c][k]
static __device__ __align__(256) __nv_bfloat16 g_wtT_hi[BATCH * CHN * CHN]; // [b][k][c]
static __device__ __align__(256) __nv_bfloat16 g_wtT_lo[BATCH * CHN * CHN];
static __device__ __align__(256) __nv_bfloat16 g_W_hi[CHN * CHN];
static __device__ __align__(256) __nv_bfloat16 g_W_lo[CHN * CHN];
static __device__ __align__(256) __nv_bfloat16 g_M_hi[BATCH * CHN * CHN];
static __device__ __align__(256) __nv_bfloat16 g_M_lo[BATCH * CHN * CHN];

// ---------------------------------------------------------------------------
// Baseline-ISA helpers (valid at compute_100 / sm_100 without 'a' features)
// ---------------------------------------------------------------------------
__device__ __forceinline__ uint32_t smem_to_u32(const void* smem_ptr) {
    uint32_t addr;
    asm("{ .reg .u64 tmp; cvta.to.shared.u64 tmp, %1; cvt.u32.u64 %0, tmp; }"
        : "=r"(addr) : "l"(smem_ptr));
    return addr;
}

__device__ __forceinline__ void cp16(uint32_t dst_smem, const void* src) {
    asm volatile("cp.async.cg.shared.global [%0], [%1], 16;\n"
                 :: "r"(dst_smem), "l"(src));
}
__device__ __forceinline__ void cp_commit() {
    asm volatile("cp.async.commit_group;\n" ::: "memory");
}
__device__ __forceinline__ void cp_wait1() {
    asm volatile("cp.async.wait_group 1;\n" ::: "memory");
}
__device__ __forceinline__ void cp_wait0() {
    asm volatile("cp.async.wait_group 0;\n" ::: "memory");
}

__device__ __forceinline__ void ldm_x4(uint32_t& r0, uint32_t& r1,
                                       uint32_t& r2, uint32_t& r3, uint32_t addr) {
    asm volatile("ldmatrix.sync.aligned.m8n8.x4.shared.b16 {%0,%1,%2,%3}, [%4];\n"
                 : "=r"(r0), "=r"(r1), "=r"(r2), "=r"(r3) : "r"(addr));
}

__device__ __forceinline__ void mma_bf16(float* c, const uint32_t* a,
                                         uint32_t b0, uint32_t b1) {
    asm volatile(
        "mma.sync.aligned.m16n8k16.row.col.f32.bf16.bf16.f32 "
        "{%0,%1,%2,%3}, {%4,%5,%6,%7}, {%8,%9}, {%0,%1,%2,%3};\n"
        : "+f"(c[0]), "+f"(c[1]), "+f"(c[2]), "+f"(c[3])
        : "r"(a[0]), "r"(a[1]), "r"(a[2]), "r"(a[3]), "r"(b0), "r"(b1));
}

__device__ __forceinline__ uint32_t sw128(uint32_t off) {
    return off ^ ((off >> 3) & 0x70);
}

// ---------------------------------------------------------------------------
// Elementwise kernels
// ---------------------------------------------------------------------------

__global__ void noop_kernel() {}   // shifts ncu's profiled launch onto the GEMM

// x (f32 [b][c][l]) -> x_hi [b][c][l], xT_hi/xT_lo [b][l][c] (tiled transpose)
__global__ void split_transpose_kernel(const float* __restrict__ x) {
    __shared__ float tile[32][33];
    const int b  = blockIdx.z;
    const int c0 = blockIdx.y * 32;
    const int l0 = blockIdx.x * 32;
    const int tx = threadIdx.x, ty = threadIdx.y;
#pragma unroll
    for (int i = 0; i < 4; i++) {
        int c = c0 + ty + i * 8;
        size_t gi = ((size_t)b * CHN + c) * SEQ + l0 + tx;
        float v = x[gi];
        tile[ty + i * 8][tx] = v;
        g_x_hi[gi] = __float2bfloat16(v);
    }
    __syncthreads();
#pragma unroll
    for (int i = 0; i < 4; i++) {
        int l = l0 + ty + i * 8;
        int c = c0 + tx;
        float v = tile[tx][ty + i * 8];
        __nv_bfloat16 h = __float2bfloat16(v);
        size_t go = ((size_t)b * SEQ + l) * CHN + c;
        g_xT_hi[go] = h;
        g_xT_lo[go] = __float2bfloat16(v - __bfloat162float(h));
    }
}

__global__ void split_f32_kernel(const float* __restrict__ src,
                                 __nv_bfloat16* __restrict__ hi,
                                 __nv_bfloat16* __restrict__ lo, int n) {
    for (int i = blockIdx.x * blockDim.x + threadIdx.x; i < n;
         i += gridDim.x * blockDim.x) {
        float v = src[i];
        __nv_bfloat16 h = __float2bfloat16(v);
        hi[i] = h;
        lo[i] = __float2bfloat16(v - __bfloat162float(h));
    }
}

// Row softmax of logits[b][c][:] -> transposed split weights wtT[b][k][c].
// Block: 32 rows (c) x one k-quarter. Warp-shuffle row reductions (redundant
// across the 4 k-quarter blocks — cheap), then 32x32 smem-transposed,
// coalesced bf16 writes of 4 k-tiles.
__global__ void __launch_bounds__(256, 1) softmax_kernel() {
    __shared__ float s_mx[32], s_inv[32];
    __shared__ uint32_t s_t[32][33];   // packed (hi | lo<<16) bf16 pair
    const int tid  = threadIdx.x;
    const int lane = tid & 31;
    const int w    = tid >> 5;         // 0..7
    const int c0   = blockIdx.x * 32;
    const int q    = blockIdx.y;       // k-quarter 0..3
    const int b    = blockIdx.z;

    // Phase A: per-row max & sum via warp shuffles (warp w owns rows 4w..4w+3).
#pragma unroll
    for (int r = 0; r < 4; r++) {
        const int row = w * 4 + r;
        const float* p = g_logits + ((size_t)(b * CHN + c0 + row)) * CHN;
        float mx = -3.4e38f;
#pragma unroll
        for (int i = 0; i < 16; i++) mx = fmaxf(mx, p[lane + 32 * i]);
#pragma unroll
        for (int s = 16; s > 0; s >>= 1)
            mx = fmaxf(mx, __shfl_xor_sync(0xFFFFFFFFu, mx, s));
        float sum = 0.0f;
#pragma unroll
        for (int i = 0; i < 16; i++) sum += __expf(p[lane + 32 * i] - mx);
#pragma unroll
        for (int s = 16; s > 0; s >>= 1)
            sum += __shfl_xor_sync(0xFFFFFFFFu, sum, s);
        if (lane == 0) { s_mx[row] = mx; s_inv[row] = 1.0f / sum; }
    }
    __syncthreads();

    // Phase B: this block's 4 k-tiles of 32x32; transpose in smem; store.
    for (int kt = q * 4; kt < q * 4 + 4; kt++) {
#pragma unroll
        for (int i = 0; i < 4; i++) {
            int cl = w + 8 * i;                 // 0..31 (row within tile)
            int k  = kt * 32 + lane;
            float v = g_logits[((size_t)(b * CHN + c0 + cl)) * CHN + k];
            float wv = __expf(v - s_mx[cl]) * s_inv[cl];
            __nv_bfloat16 h = __float2bfloat16(wv);
            __nv_bfloat16 l = __float2bfloat16(wv - __bfloat162float(h));
            s_t[cl][lane] = (uint32_t)__bfloat16_as_ushort(h) |
                            ((uint32_t)__bfloat16_as_ushort(l) << 16);
        }
        __syncthreads();
#pragma unroll
        for (int i = 0; i < 4; i++) {
            int kl = w + 8 * i;                 // k within tile
            int k  = kt * 32 + kl;
            uint32_t pk = s_t[lane][kl];
            size_t o = ((size_t)(b * CHN + k)) * CHN + c0 + lane;
            g_wtT_hi[o] = __ushort_as_bfloat16((unsigned short)(pk & 0xFFFF));
            g_wtT_lo[o] = __ushort_as_bfloat16((unsigned short)(pk >> 16));
        }
        __syncthreads();
    }
}

// ---------------------------------------------------------------------------
// NT GEMM via mma.sync (m16n8k16 bf16, fp32 accum):
//   C[m,n] = sum_seg sum_k A_seg[m,k] * B_seg[n,k] (+bias[m])
// A_seg: [M,K] K-major bf16, B_seg: [N,K] K-major bf16.
// Output: fp32 row-major C, OR bf16 hi/lo split pair (Chi/Clo).
// CTA tile 128x128, K-chunk 64, 8 warps (4x2), warp tile 32x64.
// 3-stage cp.async, single __syncthreads per chunk, and REGISTER-LEVEL
// FRAGMENT DOUBLE-BUFFERING: ldmatrix for ks+1 issued before the 16 MMAs of
// ks, giving ~130 cycles of HMMA between an LDSM and its consumer.
// __launch_bounds__(256, 1): grid-128 launches run 1 CTA/SM anyway; the
// 255-reg budget is what makes the fragment pipeline spill-free (~132 regs).
// Swizzle applied to the FULL unswizzled offset per K-step (XOR mask overlaps
// the ks*32 bits; adding after swizzling carries into the row field).
// ---------------------------------------------------------------------------
struct GemmArgs {
    const __nv_bfloat16* A0; const __nv_bfloat16* A1; const __nv_bfloat16* A2;
    const __nv_bfloat16* B0; const __nv_bfloat16* B1; const __nv_bfloat16* B2;
    long long Abatch, Bbatch, Cbatch;   // element strides per batch (z)
    int ldA, ldB, ldC;
    int Kseg, nseg;
    float* C;                            // fp32 output (if Chi == nullptr)
    __nv_bfloat16* Chi;                  // optional split-bf16 output
    __nv_bfloat16* Clo;
    const float* bias;
};

#define STAGE_BYTES 32768                   // A tile 16KB + B tile 16KB
#define GEMM_STAGES 3
#define GEMM_SMEM_TOTAL (GEMM_STAGES * STAGE_BYTES)   // 96 KB

__global__ void __launch_bounds__(256, 1)
gemm_nt_bf16(GemmArgs args) {
    extern __shared__ char smem[];
    const uint32_t smem_u32 = smem_to_u32(smem);
    const int tid  = threadIdx.x;
    const int wid  = tid >> 5;
    const int lane = tid & 31;
    const int m0 = blockIdx.y * 128;
    const int n0 = blockIdx.x * 128;
    const int bz = blockIdx.z;

    const int warp_m = wid & 3;     // 0..3 -> m offset 32*warp_m
    const int warp_n = wid >> 2;    // 0..1 -> n offset 64*warp_n

    const int cps = args.Kseg >> 6;        // chunks per segment
    const int T   = args.nseg * cps;       // total K-chunks

    // Per-thread ldmatrix UNswizzled base offsets within a stage buffer.
    const uint32_t a_off = (uint32_t)((warp_m * 32 + (lane & 15)) * 128 +
                                      (lane >> 4) * 16);
    const uint32_t b_off = (uint32_t)((warp_n * 64 + ((lane >> 4) << 3) +
                                       (lane & 7)) * 128 +
                                      ((lane >> 3) & 1) * 16);

    float acc[2][8][4];
#pragma unroll
    for (int mi = 0; mi < 2; mi++)
#pragma unroll
        for (int nt = 0; nt < 8; nt++)
#pragma unroll
            for (int r = 0; r < 4; r++) acc[mi][nt][r] = 0.0f;

    // Issue cp.async loads for K-chunk t into buffer (t % 3).
    auto issue_load = [&](int t) {
        int seg = t / cps;
        int kc  = (t - seg * cps) << 6;
        const __nv_bfloat16* Ag =
            (seg == 0 ? args.A0 : (seg == 1 ? args.A1 : args.A2)) +
            (size_t)bz * args.Abatch;
        const __nv_bfloat16* Bg =
            (seg == 0 ? args.B0 : (seg == 1 ? args.B1 : args.B2)) +
            (size_t)bz * args.Bbatch;
        uint32_t base = smem_u32 + (uint32_t)(t % GEMM_STAGES) * STAGE_BYTES;
#pragma unroll
        for (int i = 0; i < 4; i++) {
            int v   = i * 256 + tid;           // 0..1023 (16B vectors)
            int r   = v >> 3;
            int c16 = v & 7;
            uint32_t sw = sw128((uint32_t)(r * 128 + c16 * 16));
            cp16(base + sw,
                 Ag + (size_t)(m0 + r) * args.ldA + kc + c16 * 8);
            cp16(base + 16384 + sw,
                 Bg + (size_t)(n0 + r) * args.ldB + kc + c16 * 8);
        }
        cp_commit();
    };

    issue_load(0);
    if (T > 1) issue_load(1);

    // Double-buffered fragments.
    uint32_t af[2][2][4];
    uint32_t bf[2][4][4];

    for (int t = 0; t < T; t++) {
        if (t + 1 < T) cp_wait1(); else cp_wait0();
        __syncthreads();
        // Safe: buffer (t+2)%3 == (t-1)%3; this iteration's barrier guarantees
        // every thread finished compute(t-1).
        if (t + 2 < T) issue_load(t + 2);

        const uint32_t base = smem_u32 + (uint32_t)(t % GEMM_STAGES) * STAGE_BYTES;

        // Load fragments for ks=0 into slot 0.
        {
            const uint32_t aaddr = base + sw128(a_off);
            const uint32_t baddr = base + 16384 + sw128(b_off);
            ldm_x4(af[0][0][0], af[0][0][1], af[0][0][2], af[0][0][3], aaddr);
            ldm_x4(af[0][1][0], af[0][1][1], af[0][1][2], af[0][1][3], aaddr + 2048);
#pragma unroll
            for (int pj = 0; pj < 4; pj++)
                ldm_x4(bf[0][pj][0], bf[0][pj][1], bf[0][pj][2], bf[0][pj][3],
                       baddr + pj * 2048);
        }

#pragma unroll
        for (int ks = 0; ks < 4; ks++) {
            const int cur = ks & 1;
            const int nxt = cur ^ 1;
            if (ks < 3) {
                // Prefetch fragments for ks+1 into the alternate slot.
                const uint32_t aaddr = base + sw128(a_off + (ks + 1) * 32);
                const uint32_t baddr = base + 16384 + sw128(b_off + (ks + 1) * 32);
                ldm_x4(af[nxt][0][0], af[nxt][0][1], af[nxt][0][2], af[nxt][0][3],
                       aaddr);
                ldm_x4(af[nxt][1][0], af[nxt][1][1], af[nxt][1][2], af[nxt][1][3],
                       aaddr + 2048);
#pragma unroll
                for (int pj = 0; pj < 4; pj++)
                    ldm_x4(bf[nxt][pj][0], bf[nxt][pj][1], bf[nxt][pj][2],
                           bf[nxt][pj][3], baddr + pj * 2048);
            }
#pragma unroll
            for (int mi = 0; mi < 2; mi++)
#pragma unroll
                for (int nt = 0; nt < 8; nt++)
                    mma_bf16(acc[mi][nt], af[cur][mi],
                             bf[cur][nt >> 1][(nt & 1) * 2 + 0],
                             bf[cur][nt >> 1][(nt & 1) * 2 + 1]);
        }
    }

    // Epilogue.
    const int mrow = m0 + warp_m * 32;
    const int ncol = n0 + warp_n * 64 + (lane & 3) * 2;
    const int mg   = lane >> 2;

    if (args.Chi) {
        // Split-bf16 output (fused split of M).
        __nv_bfloat16* Hb = args.Chi + (size_t)bz * args.Cbatch;
        __nv_bfloat16* Lb = args.Clo + (size_t)bz * args.Cbatch;
#pragma unroll
        for (int mi = 0; mi < 2; mi++) {
            int mA = mrow + mi * 16 + mg;
            int mB = mA + 8;
            float bvA = args.bias ? args.bias[mA] : 0.0f;
            float bvB = args.bias ? args.bias[mB] : 0.0f;
#pragma unroll
            for (int nt = 0; nt < 8; nt++) {
                int n = ncol + nt * 8;
                float v0 = acc[mi][nt][0] + bvA, v1 = acc[mi][nt][1] + bvA;
                float v2 = acc[mi][nt][2] + bvB, v3 = acc[mi][nt][3] + bvB;
                __nv_bfloat162 hA, lA, hB, lB;
                hA.x = __float2bfloat16(v0); hA.y = __float2bfloat16(v1);
                lA.x = __float2bfloat16(v0 - __bfloat162float(hA.x));
                lA.y = __float2bfloat16(v1 - __bfloat162float(hA.y));
                hB.x = __float2bfloat16(v2); hB.y = __float2bfloat16(v3);
                lB.x = __float2bfloat16(v2 - __bfloat162float(hB.x));
                lB.y = __float2bfloat16(v3 - __bfloat162float(hB.y));
                *reinterpret_cast<__nv_bfloat162*>(Hb + (size_t)mA * args.ldC + n) = hA;
                *reinterpret_cast<__nv_bfloat162*>(Lb + (size_t)mA * args.ldC + n) = lA;
                *reinterpret_cast<__nv_bfloat162*>(Hb + (size_t)mB * args.ldC + n) = hB;
                *reinterpret_cast<__nv_bfloat162*>(Lb + (size_t)mB * args.ldC + n) = lB;
            }
        }
    } else {
        float* Cb = args.C + (size_t)bz * args.Cbatch;
#pragma unroll
        for (int mi = 0; mi < 2; mi++) {
            int mA = mrow + mi * 16 + mg;
            int mB = mA + 8;
            float bvA = args.bias ? args.bias[mA] : 0.0f;
            float bvB = args.bias ? args.bias[mB] : 0.0f;
            float* rowA = Cb + (size_t)mA * args.ldC;
            float* rowB = Cb + (size_t)mB * args.ldC;
#pragma unroll
            for (int nt = 0; nt < 8; nt++) {
                int n = ncol + nt * 8;
                float2 vA = make_float2(acc[mi][nt][0] + bvA, acc[mi][nt][1] + bvA);
                float2 vB = make_float2(acc[mi][nt][2] + bvB, acc[mi][nt][3] + bvB);
                *reinterpret_cast<float2*>(rowA + n) = vA;
                *reinterpret_cast<float2*>(rowB + n) = vB;
            }
        }
    }
}

// ---------------------------------------------------------------------------
// Host launcher
// ---------------------------------------------------------------------------
extern "C" void kernel_launch(void* const* d_in, const int* in_sizes, int n_in,
                              void* d_out, int out_size) {
    (void)out_size;
    // Identify inputs by unique element counts (order-proof).
    const float* x    = nullptr;   // 8*512*4096 = 16777216
    const float* W    = nullptr;   // 512*512    = 262144
    const float* bias = nullptr;   // 512
    for (int i = 0; i < n_in; i++) {
        if (in_sizes[i] == BATCH * CHN * SEQ)      x    = (const float*)d_in[i];
        else if (in_sizes[i] == CHN * CHN)         W    = (const float*)d_in[i];
        else if (in_sizes[i] == CHN)               bias = (const float*)d_in[i];
    }
    if (!x || !W || !bias) return;   // clean failure instead of wild deref
    float* out = (float*)d_out;

    void *p_x_hi, *p_xT_hi, *p_xT_lo, *p_logits, *p_wtT_hi, *p_wtT_lo;
    void *p_W_hi, *p_W_lo, *p_M_hi, *p_M_lo;
    cudaGetSymbolAddress(&p_x_hi,  g_x_hi);
    cudaGetSymbolAddress(&p_xT_hi, g_xT_hi);
    cudaGetSymbolAddress(&p_xT_lo, g_xT_lo);
    cudaGetSymbolAddress(&p_logits, g_logits);
    cudaGetSymbolAddress(&p_wtT_hi, g_wtT_hi);
    cudaGetSymbolAddress(&p_wtT_lo, g_wtT_lo);
    cudaGetSymbolAddress(&p_W_hi, g_W_hi);
    cudaGetSymbolAddress(&p_W_lo, g_W_lo);
    cudaGetSymbolAddress(&p_M_hi, g_M_hi);
    cudaGetSymbolAddress(&p_M_lo, g_M_lo);

    cudaFuncSetAttribute(gemm_nt_bf16,
                         cudaFuncAttributeMaxDynamicSharedMemorySize,
                         GEMM_SMEM_TOTAL);

    // 1) split + transpose x ; split W ; profiling-alignment noop
    split_transpose_kernel<<<dim3(SEQ / 32, CHN / 32, BATCH), dim3(32, 8)>>>(x);
    split_f32_kernel<<<256, 256>>>(W, (__nv_bfloat16*)p_W_hi, (__nv_bfloat16*)p_W_lo,
                                   CHN * CHN);
    noop_kernel<<<1, 32>>>();   // keeps the ncu-profiled launch on the logits GEMM

    // 2) logits = x_hi @ x_hi^T  (per batch, K = 4096)
    {
        GemmArgs a{};
        a.A0 = a.A1 = a.A2 = (const __nv_bfloat16*)p_x_hi;
        a.B0 = a.B1 = a.B2 = (const __nv_bfloat16*)p_x_hi;
        a.Abatch = a.Bbatch = (long long)CHN * SEQ;
        a.ldA = a.ldB = SEQ;
        a.Kseg = SEQ; a.nseg = 1;
        a.C = (float*)p_logits; a.Cbatch = (long long)CHN * CHN; a.ldC = CHN;
        a.Chi = nullptr; a.Clo = nullptr;
        a.bias = nullptr;
        gemm_nt_bf16<<<dim3(CHN / 128, CHN / 128, BATCH), 256, GEMM_SMEM_TOTAL>>>(a);
    }

    // 3) softmax rows -> transposed split weights (k-split x4, coalesced)
    softmax_kernel<<<dim3(CHN / 32, 4, BATCH), 256>>>();

    // 4) M = W @ weights  (split-bf16, 3 segments, K = 512 each)
    //    Epilogue writes M_hi / M_lo directly (split fused).
    {
        GemmArgs a{};
        a.A0 = (const __nv_bfloat16*)p_W_hi;
        a.A1 = (const __nv_bfloat16*)p_W_hi;
        a.A2 = (const __nv_bfloat16*)p_W_lo;
        a.B0 = (const __nv_bfloat16*)p_wtT_hi;
        a.B1 = (const __nv_bfloat16*)p_wtT_lo;
        a.B2 = (const __nv_bfloat16*)p_wtT_hi;
        a.Abatch = 0; a.Bbatch = (long long)CHN * CHN;
        a.ldA = CHN; a.ldB = CHN;
        a.Kseg = CHN; a.nseg = 3;
        a.C = nullptr;
        a.Chi = (__nv_bfloat16*)p_M_hi; a.Clo = (__nv_bfloat16*)p_M_lo;
        a.Cbatch = (long long)CHN * CHN; a.ldC = CHN;
        a.bias = nullptr;
        gemm_nt_bf16<<<dim3(CHN / 128, CHN / 128, BATCH), 256, GEMM_SMEM_TOTAL>>>(a);
    }

    // 5) out = M @ x + b  (split-bf16, 3 segments, K = 512 each)
    {
        GemmArgs a{};
        a.A0 = (const __nv_bfloat16*)p_M_hi;
        a.A1 = (const __nv_bfloat16*)p_M_hi;
        a.A2 = (const __nv_bfloat16*)p_M_lo;
        a.B0 = (const __nv_bfloat16*)p_xT_hi;
        a.B1 = (const __nv_bfloat16*)p_xT_lo;
        a.B2 = (const __nv_bfloat16*)p_xT_hi;
        a.Abatch = (long long)CHN * CHN; a.Bbatch = (long long)SEQ * CHN;
        a.ldA = CHN; a.ldB = CHN;
        a.Kseg = CHN; a.nseg = 3;
        a.C = out; a.Cbatch = (long long)CHN * SEQ; a.ldC = SEQ;
        a.Chi = nullptr; a.Clo = nullptr;
        a.bias = bias;
        gemm_nt_bf16<<<dim3(SEQ / 128, CHN / 128, BATCH), 256, GEMM_SMEM_TOTAL>>>(a);
    }
}

// round 16
// speedup vs baseline: 1.2286x; 1.2286x over previous
#include <cuda_runtime.h>
#include <cuda_bf16.h>
#include <cstdint>
#include <cstddef>

#define BATCH 8
#define CHN   512
#define SEQ   4096
#define LSZ   ((size_t)BATCH * CHN * CHN)   // one logits partial buffer

// ---------------------------------------------------------------------------
// Device scratch (allocation-free rule: __device__ globals)
// ---------------------------------------------------------------------------
static __device__ __align__(256) __nv_bfloat16 g_x_hi [BATCH * CHN * SEQ];  // [b][c][l]
static __device__ __align__(256) __nv_bfloat16 g_xT_hi[BATCH * SEQ * CHN];  // [b][l][c]
static __device__ __align__(256) __nv_bfloat16 g_xT_lo[BATCH * SEQ * CHN];
static __device__ __align__(256) float         g_logits[2 * BATCH * CHN * CHN]; // 2 K-slices
static __device__ __align__(256) __nv_bfloat16 g_wtT_hi[BATCH * CHN * CHN]; // [b][k][c]
static __device__ __align__(256) __nv_bfloat16 g_wtT_lo[BATCH * CHN * CHN];
static __device__ __align__(256) __nv_bfloat16 g_W_hi[CHN * CHN];
static __device__ __align__(256) __nv_bfloat16 g_W_lo[CHN * CHN];
static __device__ __align__(256) __nv_bfloat16 g_M_hi[BATCH * CHN * CHN];
static __device__ __align__(256) __nv_bfloat16 g_M_lo[BATCH * CHN * CHN];

// ---------------------------------------------------------------------------
// Baseline-ISA helpers (valid at compute_100 / sm_100 without 'a' features)
// ---------------------------------------------------------------------------
__device__ __forceinline__ uint32_t smem_to_u32(const void* smem_ptr) {
    uint32_t addr;
    asm("{ .reg .u64 tmp; cvta.to.shared.u64 tmp, %1; cvt.u32.u64 %0, tmp; }"
        : "=r"(addr) : "l"(smem_ptr));
    return addr;
}

__device__ __forceinline__ void cp16(uint32_t dst_smem, const void* src) {
    asm volatile("cp.async.cg.shared.global [%0], [%1], 16;\n"
                 :: "r"(dst_smem), "l"(src));
}
__device__ __forceinline__ void cp_commit() {
    asm volatile("cp.async.commit_group;\n" ::: "memory");
}
__device__ __forceinline__ void cp_wait1() {
    asm volatile("cp.async.wait_group 1;\n" ::: "memory");
}
__device__ __forceinline__ void cp_wait0() {
    asm volatile("cp.async.wait_group 0;\n" ::: "memory");
}

__device__ __forceinline__ void ldm_x4(uint32_t& r0, uint32_t& r1,
                                       uint32_t& r2, uint32_t& r3, uint32_t addr) {
    asm volatile("ldmatrix.sync.aligned.m8n8.x4.shared.b16 {%0,%1,%2,%3}, [%4];\n"
                 : "=r"(r0), "=r"(r1), "=r"(r2), "=r"(r3) : "r"(addr));
}

__device__ __forceinline__ void mma_bf16(float* c, const uint32_t* a,
                                         uint32_t b0, uint32_t b1) {
    asm volatile(
        "mma.sync.aligned.m16n8k16.row.col.f32.bf16.bf16.f32 "
        "{%0,%1,%2,%3}, {%4,%5,%6,%7}, {%8,%9}, {%0,%1,%2,%3};\n"
        : "+f"(c[0]), "+f"(c[1]), "+f"(c[2]), "+f"(c[3])
        : "r"(a[0]), "r"(a[1]), "r"(a[2]), "r"(a[3]), "r"(b0), "r"(b1));
}

__device__ __forceinline__ uint32_t sw128(uint32_t off) {
    return off ^ ((off >> 3) & 0x70);
}

// ---------------------------------------------------------------------------
// Elementwise kernels
// ---------------------------------------------------------------------------

__global__ void noop_kernel() {}   // keeps ncu's profiled launch on the logits GEMM

// x (f32 [b][c][l]) -> x_hi [b][c][l], xT_hi/xT_lo [b][l][c] (tiled transpose)
__global__ void split_transpose_kernel(const float* __restrict__ x) {
    __shared__ float tile[32][33];
    const int b  = blockIdx.z;
    const int c0 = blockIdx.y * 32;
    const int l0 = blockIdx.x * 32;
    const int tx = threadIdx.x, ty = threadIdx.y;
#pragma unroll
    for (int i = 0; i < 4; i++) {
        int c = c0 + ty + i * 8;
        size_t gi = ((size_t)b * CHN + c) * SEQ + l0 + tx;
        float v = x[gi];
        tile[ty + i * 8][tx] = v;
        g_x_hi[gi] = __float2bfloat16(v);
    }
    __syncthreads();
#pragma unroll
    for (int i = 0; i < 4; i++) {
        int l = l0 + ty + i * 8;
        int c = c0 + tx;
        float v = tile[tx][ty + i * 8];
        __nv_bfloat16 h = __float2bfloat16(v);
        size_t go = ((size_t)b * SEQ + l) * CHN + c;
        g_xT_hi[go] = h;
        g_xT_lo[go] = __float2bfloat16(v - __bfloat162float(h));
    }
}

__global__ void split_f32_kernel(const float* __restrict__ src,
                                 __nv_bfloat16* __restrict__ hi,
                                 __nv_bfloat16* __restrict__ lo, int n) {
    for (int i = blockIdx.x * blockDim.x + threadIdx.x; i < n;
         i += gridDim.x * blockDim.x) {
        float v = src[i];
        __nv_bfloat16 h = __float2bfloat16(v);
        hi[i] = h;
        lo[i] = __float2bfloat16(v - __bfloat162float(h));
    }
}

// Row softmax of (logits partial0 + partial1)[b][c][:] -> transposed split
// weights wtT[b][k][c]. Block: 32 rows (c) x one k-quarter. Warp-shuffle row
// reductions (redundant across k-quarter blocks — cheap), then 32x32
// smem-transposed, coalesced bf16 writes of 4 k-tiles.
__global__ void __launch_bounds__(256, 1) softmax_kernel() {
    __shared__ float s_mx[32], s_inv[32];
    __shared__ uint32_t s_t[32][33];   // packed (hi | lo<<16) bf16 pair
    const int tid  = threadIdx.x;
    const int lane = tid & 31;
    const int w    = tid >> 5;         // 0..7
    const int c0   = blockIdx.x * 32;
    const int q    = blockIdx.y;       // k-quarter 0..3
    const int b    = blockIdx.z;

    // Phase A: per-row max & sum via warp shuffles (warp w owns rows 4w..4w+3).
#pragma unroll
    for (int r = 0; r < 4; r++) {
        const int row = w * 4 + r;
        const float* p = g_logits + ((size_t)(b * CHN + c0 + row)) * CHN;
        const float* p2 = p + LSZ;
        float mx = -3.4e38f;
#pragma unroll
        for (int i = 0; i < 16; i++)
            mx = fmaxf(mx, p[lane + 32 * i] + p2[lane + 32 * i]);
#pragma unroll
        for (int s = 16; s > 0; s >>= 1)
            mx = fmaxf(mx, __shfl_xor_sync(0xFFFFFFFFu, mx, s));
        float sum = 0.0f;
#pragma unroll
        for (int i = 0; i < 16; i++)
            sum += __expf(p[lane + 32 * i] + p2[lane + 32 * i] - mx);
#pragma unroll
        for (int s = 16; s > 0; s >>= 1)
            sum += __shfl_xor_sync(0xFFFFFFFFu, sum, s);
        if (lane == 0) { s_mx[row] = mx; s_inv[row] = 1.0f / sum; }
    }
    __syncthreads();

    // Phase B: this block's 4 k-tiles of 32x32; transpose in smem; store.
    for (int kt = q * 4; kt < q * 4 + 4; kt++) {
#pragma unroll
        for (int i = 0; i < 4; i++) {
            int cl = w + 8 * i;                 // 0..31 (row within tile)
            int k  = kt * 32 + lane;
            size_t idx = ((size_t)(b * CHN + c0 + cl)) * CHN + k;
            float v = g_logits[idx] + g_logits[idx + LSZ];
            float wv = __expf(v - s_mx[cl]) * s_inv[cl];
            __nv_bfloat16 h = __float2bfloat16(wv);
            __nv_bfloat16 l = __float2bfloat16(wv - __bfloat162float(h));
            s_t[cl][lane] = (uint32_t)__bfloat16_as_ushort(h) |
                            ((uint32_t)__bfloat16_as_ushort(l) << 16);
        }
        __syncthreads();
#pragma unroll
        for (int i = 0; i < 4; i++) {
            int kl = w + 8 * i;                 // k within tile
            int k  = kt * 32 + kl;
            uint32_t pk = s_t[lane][kl];
            size_t o = ((size_t)(b * CHN + k)) * CHN + c0 + lane;
            g_wtT_hi[o] = __ushort_as_bfloat16((unsigned short)(pk & 0xFFFF));
            g_wtT_lo[o] = __ushort_as_bfloat16((unsigned short)(pk >> 16));
        }
        __syncthreads();
    }
}

// ---------------------------------------------------------------------------
// NT GEMM via mma.sync (m16n8k16 bf16, fp32 accum):
//   C[m,n] = sum_seg sum_k A_seg[m,k] * B_seg[n,k] (+bias[m])
// A_seg: [M,K] K-major bf16, B_seg: [N,K] K-major bf16.
// Output: fp32 row-major C, OR bf16 hi/lo split pair (Chi/Clo).
// CTA tile 128x128, K-chunk 64, 8 warps (4x2), warp tile 32x64.
// 3-stage cp.async, single __syncthreads per chunk (R13 form — measured best;
// hand fragment pipelining regressed in R15 and is NOT used).
// Optional split-K: blockIdx.z = slice*nbz + bz; slice handles K range
// [slice*Kseg/kslices, ...) and writes to C + slice*Csplit.
// __launch_bounds__(256, 2): 2 CTAs/SM (192 KB smem, 128 regs) — load-bearing
// for the grid-1024 final GEMM and the 256-CTA split-K logits GEMM.
// Swizzle applied to the FULL unswizzled offset per K-step (XOR mask overlaps
// the ks*32 bits; adding after swizzling carries into the row field).
// ---------------------------------------------------------------------------
struct GemmArgs {
    const __nv_bfloat16* A0; const __nv_bfloat16* A1; const __nv_bfloat16* A2;
    const __nv_bfloat16* B0; const __nv_bfloat16* B1; const __nv_bfloat16* B2;
    long long Abatch, Bbatch, Cbatch;   // element strides per batch
    long long Csplit;                    // element stride per K-slice
    int nbz;                             // batches in grid z
    int kslices;                         // K-split factor (1 or 2)
    int ldA, ldB, ldC;
    int Kseg, nseg;
    float* C;                            // fp32 output (if Chi == nullptr)
    __nv_bfloat16* Chi;                  // optional split-bf16 output
    __nv_bfloat16* Clo;
    const float* bias;
};

#define STAGE_BYTES 32768                   // A tile 16KB + B tile 16KB
#define GEMM_STAGES 3
#define GEMM_SMEM_TOTAL (GEMM_STAGES * STAGE_BYTES)   // 96 KB

__global__ void __launch_bounds__(256, 2)
gemm_nt_bf16(GemmArgs args) {
    extern __shared__ char smem[];
    const uint32_t smem_u32 = smem_to_u32(smem);
    const int tid  = threadIdx.x;
    const int wid  = tid >> 5;
    const int lane = tid & 31;
    const int m0 = blockIdx.y * 128;
    const int n0 = blockIdx.x * 128;
    const int bz    = (int)blockIdx.z % args.nbz;
    const int slice = (int)blockIdx.z / args.nbz;

    const int warp_m = wid & 3;     // 0..3 -> m offset 32*warp_m
    const int warp_n = wid >> 2;    // 0..1 -> n offset 64*warp_n

    const int sliceK = args.Kseg / args.kslices;
    const int kbeg   = slice * sliceK;
    const int cps = sliceK >> 6;           // chunks per segment (this slice)
    const int T   = args.nseg * cps;       // total K-chunks

    // Per-thread ldmatrix UNswizzled base offsets within a stage buffer.
    const uint32_t a_off = (uint32_t)((warp_m * 32 + (lane & 15)) * 128 +
                                      (lane >> 4) * 16);
    const uint32_t b_off = (uint32_t)((warp_n * 64 + ((lane >> 4) << 3) +
                                       (lane & 7)) * 128 +
                                      ((lane >> 3) & 1) * 16);

    float acc[2][8][4];
#pragma unroll
    for (int mi = 0; mi < 2; mi++)
#pragma unroll
        for (int nt = 0; nt < 8; nt++)
#pragma unroll
            for (int r = 0; r < 4; r++) acc[mi][nt][r] = 0.0f;

    // Issue cp.async loads for K-chunk t into buffer (t % 3).
    auto issue_load = [&](int t) {
        int seg = t / cps;
        int kc  = kbeg + ((t - seg * cps) << 6);
        const __nv_bfloat16* Ag =
            (seg == 0 ? args.A0 : (seg == 1 ? args.A1 : args.A2)) +
            (size_t)bz * args.Abatch;
        const __nv_bfloat16* Bg =
            (seg == 0 ? args.B0 : (seg == 1 ? args.B1 : args.B2)) +
            (size_t)bz * args.Bbatch;
        uint32_t base = smem_u32 + (uint32_t)(t % GEMM_STAGES) * STAGE_BYTES;
#pragma unroll
        for (int i = 0; i < 4; i++) {
            int v   = i * 256 + tid;           // 0..1023 (16B vectors)
            int r   = v >> 3;
            int c16 = v & 7;
            uint32_t sw = sw128((uint32_t)(r * 128 + c16 * 16));
            cp16(base + sw,
                 Ag + (size_t)(m0 + r) * args.ldA + kc + c16 * 8);
            cp16(base + 16384 + sw,
                 Bg + (size_t)(n0 + r) * args.ldB + kc + c16 * 8);
        }
        cp_commit();
    };

    issue_load(0);
    if (T > 1) issue_load(1);

    for (int t = 0; t < T; t++) {
        if (t + 1 < T) cp_wait1(); else cp_wait0();
        __syncthreads();
        // Safe: buffer (t+2)%3 == (t-1)%3; this iteration's barrier guarantees
        // every thread finished compute(t-1).
        if (t + 2 < T) issue_load(t + 2);

        const uint32_t base = smem_u32 + (uint32_t)(t % GEMM_STAGES) * STAGE_BYTES;

#pragma unroll
        for (int ks = 0; ks < 4; ks++) {
            const uint32_t aaddr = base + sw128(a_off + ks * 32);
            const uint32_t baddr = base + 16384 + sw128(b_off + ks * 32);
            uint32_t a[2][4];
            ldm_x4(a[0][0], a[0][1], a[0][2], a[0][3], aaddr);
            ldm_x4(a[1][0], a[1][1], a[1][2], a[1][3], aaddr + 2048);
            uint32_t b[4][4];
#pragma unroll
            for (int pj = 0; pj < 4; pj++)
                ldm_x4(b[pj][0], b[pj][1], b[pj][2], b[pj][3],
                       baddr + pj * 2048);
#pragma unroll
            for (int mi = 0; mi < 2; mi++)
#pragma unroll
                for (int nt = 0; nt < 8; nt++)
                    mma_bf16(acc[mi][nt], a[mi],
                             b[nt >> 1][(nt & 1) * 2 + 0],
                             b[nt >> 1][(nt & 1) * 2 + 1]);
        }
    }

    // Epilogue.
    const int mrow = m0 + warp_m * 32;
    const int ncol = n0 + warp_n * 64 + (lane & 3) * 2;
    const int mg   = lane >> 2;
    const size_t cofs = (size_t)bz * args.Cbatch + (size_t)slice * args.Csplit;

    if (args.Chi) {
        // Split-bf16 output (fused split of M).
        __nv_bfloat16* Hb = args.Chi + cofs;
        __nv_bfloat16* Lb = args.Clo + cofs;
#pragma unroll
        for (int mi = 0; mi < 2; mi++) {
            int mA = mrow + mi * 16 + mg;
            int mB = mA + 8;
            float bvA = args.bias ? args.bias[mA] : 0.0f;
            float bvB = args.bias ? args.bias[mB] : 0.0f;
#pragma unroll
            for (int nt = 0; nt < 8; nt++) {
                int n = ncol + nt * 8;
                float v0 = acc[mi][nt][0] + bvA, v1 = acc[mi][nt][1] + bvA;
                float v2 = acc[mi][nt][2] + bvB, v3 = acc[mi][nt][3] + bvB;
                __nv_bfloat162 hA, lA, hB, lB;
                hA.x = __float2bfloat16(v0); hA.y = __float2bfloat16(v1);
                lA.x = __float2bfloat16(v0 - __bfloat162float(hA.x));
                lA.y = __float2bfloat16(v1 - __bfloat162float(hA.y));
                hB.x = __float2bfloat16(v2); hB.y = __float2bfloat16(v3);
                lB.x = __float2bfloat16(v2 - __bfloat162float(hB.x));
                lB.y = __float2bfloat16(v3 - __bfloat162float(hB.y));
                *reinterpret_cast<__nv_bfloat162*>(Hb + (size_t)mA * args.ldC + n) = hA;
                *reinterpret_cast<__nv_bfloat162*>(Lb + (size_t)mA * args.ldC + n) = lA;
                *reinterpret_cast<__nv_bfloat162*>(Hb + (size_t)mB * args.ldC + n) = hB;
                *reinterpret_cast<__nv_bfloat162*>(Lb + (size_t)mB * args.ldC + n) = lB;
            }
        }
    } else {
        float* Cb = args.C + cofs;
#pragma unroll
        for (int mi = 0; mi < 2; mi++) {
            int mA = mrow + mi * 16 + mg;
            int mB = mA + 8;
            float bvA = args.bias ? args.bias[mA] : 0.0f;
            float bvB = args.bias ? args.bias[mB] : 0.0f;
            float* rowA = Cb + (size_t)mA * args.ldC;
            float* rowB = Cb + (size_t)mB * args.ldC;
#pragma unroll
            for (int nt = 0; nt < 8; nt++) {
                int n = ncol + nt * 8;
                float2 vA = make_float2(acc[mi][nt][0] + bvA, acc[mi][nt][1] + bvA);
                float2 vB = make_float2(acc[mi][nt][2] + bvB, acc[mi][nt][3] + bvB);
                *reinterpret_cast<float2*>(rowA + n) = vA;
                *reinterpret_cast<float2*>(rowB + n) = vB;
            }
        }
    }
}

// ---------------------------------------------------------------------------
// Host launcher
// ---------------------------------------------------------------------------
extern "C" void kernel_launch(void* const* d_in, const int* in_sizes, int n_in,
                              void* d_out, int out_size) {
    (void)out_size;
    // Identify inputs by unique element counts (order-proof).
    const float* x    = nullptr;   // 8*512*4096 = 16777216
    const float* W    = nullptr;   // 512*512    = 262144
    const float* bias = nullptr;   // 512
    for (int i = 0; i < n_in; i++) {
        if (in_sizes[i] == BATCH * CHN * SEQ)      x    = (const float*)d_in[i];
        else if (in_sizes[i] == CHN * CHN)         W    = (const float*)d_in[i];
        else if (in_sizes[i] == CHN)               bias = (const float*)d_in[i];
    }
    if (!x || !W || !bias) return;   // clean failure instead of wild deref
    float* out = (float*)d_out;

    void *p_x_hi, *p_xT_hi, *p_xT_lo, *p_logits, *p_wtT_hi, *p_wtT_lo;
    void *p_W_hi, *p_W_lo, *p_M_hi, *p_M_lo;
    cudaGetSymbolAddress(&p_x_hi,  g_x_hi);
    cudaGetSymbolAddress(&p_xT_hi, g_xT_hi);
    cudaGetSymbolAddress(&p_xT_lo, g_xT_lo);
    cudaGetSymbolAddress(&p_logits, g_logits);
    cudaGetSymbolAddress(&p_wtT_hi, g_wtT_hi);
    cudaGetSymbolAddress(&p_wtT_lo, g_wtT_lo);
    cudaGetSymbolAddress(&p_W_hi, g_W_hi);
    cudaGetSymbolAddress(&p_W_lo, g_W_lo);
    cudaGetSymbolAddress(&p_M_hi, g_M_hi);
    cudaGetSymbolAddress(&p_M_lo, g_M_lo);

    cudaFuncSetAttribute(gemm_nt_bf16,
                         cudaFuncAttributeMaxDynamicSharedMemorySize,
                         GEMM_SMEM_TOTAL);

    // 1) split + transpose x ; split W ; profiling-alignment noop
    split_transpose_kernel<<<dim3(SEQ / 32, CHN / 32, BATCH), dim3(32, 8)>>>(x);
    split_f32_kernel<<<256, 256>>>(W, (__nv_bfloat16*)p_W_hi, (__nv_bfloat16*)p_W_lo,
                                   CHN * CHN);
    noop_kernel<<<1, 32>>>();   // keeps the ncu-profiled launch on the logits GEMM

    // 2) logits = x_hi @ x_hi^T  (per batch, K = 4096, split-K x2 -> 256 CTAs,
    //    2 CTAs/SM, one wave; partials summed in softmax)
    {
        GemmArgs a{};
        a.A0 = a.A1 = a.A2 = (const __nv_bfloat16*)p_x_hi;
        a.B0 = a.B1 = a.B2 = (const __nv_bfloat16*)p_x_hi;
        a.Abatch = a.Bbatch = (long long)CHN * SEQ;
        a.ldA = a.ldB = SEQ;
        a.Kseg = SEQ; a.nseg = 1;
        a.C = (float*)p_logits; a.Cbatch = (long long)CHN * CHN; a.ldC = CHN;
        a.Csplit = (long long)LSZ; a.nbz = BATCH; a.kslices = 2;
        a.Chi = nullptr; a.Clo = nullptr;
        a.bias = nullptr;
        gemm_nt_bf16<<<dim3(CHN / 128, CHN / 128, BATCH * 2), 256,
                       GEMM_SMEM_TOTAL>>>(a);
    }

    // 3) softmax rows (sum of 2 partials) -> transposed split weights
    softmax_kernel<<<dim3(CHN / 32, 4, BATCH), 256>>>();

    // 4) M = W @ weights  (split-bf16, 3 segments, K = 512 each)
    //    Epilogue writes M_hi / M_lo directly (split fused).
    {
        GemmArgs a{};
        a.A0 = (const __nv_bfloat16*)p_W_hi;
        a.A1 = (const __nv_bfloat16*)p_W_hi;
        a.A2 = (const __nv_bfloat16*)p_W_lo;
        a.B0 = (const __nv_bfloat16*)p_wtT_hi;
        a.B1 = (const __nv_bfloat16*)p_wtT_lo;
        a.B2 = (const __nv_bfloat16*)p_wtT_hi;
        a.Abatch = 0; a.Bbatch = (long long)CHN * CHN;
        a.ldA = CHN; a.ldB = CHN;
        a.Kseg = CHN; a.nseg = 3;
        a.C = nullptr;
        a.Chi = (__nv_bfloat16*)p_M_hi; a.Clo = (__nv_bfloat16*)p_M_lo;
        a.Cbatch = (long long)CHN * CHN; a.ldC = CHN;
        a.Csplit = 0; a.nbz = BATCH; a.kslices = 1;
        a.bias = nullptr;
        gemm_nt_bf16<<<dim3(CHN / 128, CHN / 128, BATCH), 256, GEMM_SMEM_TOTAL>>>(a);
    }

    // 5) out = M @ x + b  (split-bf16, 3 segments, K = 512 each)
    {
        GemmArgs a{};
        a.A0 = (const __nv_bfloat16*)p_M_hi;
        a.A1 = (const __nv_bfloat16*)p_M_hi;
        a.A2 = (const __nv_bfloat16*)p_M_lo;
        a.B0 = (const __nv_bfloat16*)p_xT_hi;
        a.B1 = (const __nv_bfloat16*)p_xT_lo;
        a.B2 = (const __nv_bfloat16*)p_xT_hi;
        a.Abatch = (long long)CHN * CHN; a.Bbatch = (long long)SEQ * CHN;
        a.ldA = CHN; a.ldB = CHN;
        a.Kseg = CHN; a.nseg = 3;
        a.C = out; a.Cbatch = (long long)CHN * SEQ; a.ldC = SEQ;
        a.Csplit = 0; a.nbz = BATCH; a.kslices = 1;
        a.Chi = nullptr; a.Clo = nullptr;
        a.bias = bias;
        gemm_nt_bf16<<<dim3(SEQ / 128, CHN / 128, BATCH), 256, GEMM_SMEM_TOTAL>>>(a);
    }
}